// round 9
// baseline (speedup 1.0000x reference)
#include <cuda_runtime.h>

#define SC 0.70710678118654752f

// ---------------- filter constants ----------------
__constant__ float cG0B_E[7] = { 0.00325314f,  0.03466035f, -0.11720389f,  0.75614564f,  0.01186609f,  0.02382538f, -0.00543948f};
__constant__ float cG0B_O[7] = {-0.00388321f, -0.03887280f,  0.27529538f,  0.56881042f, -0.10671180f,  0.01702522f, -0.00455690f};
__constant__ float cG0A_E[7] = {-0.00455690f,  0.01702522f, -0.10671180f,  0.56881042f,  0.27529538f, -0.03887280f, -0.00388321f};
__constant__ float cG0A_O[7] = {-0.00543948f,  0.02382538f,  0.01186609f,  0.75614564f, -0.11720389f,  0.03466035f,  0.00325314f};
__constant__ float cG1B_E[7] = {-0.00455690f,  0.01702522f, -0.10671180f,  0.56881042f,  0.27529538f, -0.03887280f, -0.00388321f};
__constant__ float cG1B_O[7] = { 0.00543948f, -0.02382538f, -0.01186609f, -0.75614564f,  0.11720389f, -0.03466035f, -0.00325314f};
__constant__ float cG1A_E[7] = {-0.00325314f, -0.03466035f,  0.11720389f, -0.75614564f, -0.01186609f, -0.02382538f,  0.00543948f};
__constant__ float cG1A_O[7] = {-0.00388321f, -0.03887280f,  0.27529538f,  0.56881042f, -0.10671180f,  0.01702522f, -0.00455690f};

__constant__ float cG0O[7] = {-0.0107142857142857f, -0.0535714285714286f, 0.2607142857142857f,
                               0.6071428571428571f,  0.2607142857142857f, -0.0535714285714286f,
                              -0.0107142857142857f};
__constant__ float cG1O[5] = {-0.05f, -0.25f, 0.6f, -0.25f, -0.05f};

// ---------------- planar scratch [c][b][H][W] ----------------
#define P256 (256*256)
#define P512 (512*512)
__device__ float g_lowp[3*8*P256];
__device__ float g_LH1[3*8*P256];
__device__ float g_HL1[3*8*P256];
__device__ float g_HH1[3*8*P256];
__device__ float g_Z [3*8*P512];
__device__ float g_LH0[3*8*P512];
__device__ float g_HL0[3*8*P512];
__device__ float g_HH0[3*8*P512];

__device__ __forceinline__ int refl(int x, int L) {
    x = (x < 0) ? (-1 - x) : x;
    return (x >= L) ? (2 * L - 1 - x) : x;
}

// ---------------- kP: planarize low ----------------
__global__ void kP(const float* __restrict__ low) {
    int wt = threadIdx.x;         // 0..63
    int i  = blockIdx.x;          // 0..255
    int b  = blockIdx.y;          // 0..7
    const float4* p = reinterpret_cast<const float4*>(low + (((b * 256) + i) * 256 + 4 * wt) * 3);
    float4 v0 = __ldg(p), v1 = __ldg(p + 1), v2 = __ldg(p + 2);
    int o = i * 256 + 4 * wt;
    *reinterpret_cast<float4*>(g_lowp + (0 * 8 + b) * P256 + o) = make_float4(v0.x, v0.w, v1.z, v2.y);
    *reinterpret_cast<float4*>(g_lowp + (1 * 8 + b) * P256 + o) = make_float4(v0.y, v1.x, v1.w, v2.z);
    *reinterpret_cast<float4*>(g_lowp + (2 * 8 + b) * P256 + o) = make_float4(v0.z, v1.y, v2.x, v2.w);
}

// ---------------- c2q expansion ----------------
__device__ __forceinline__ void c2q_store(float* plane, int W, int r0, int c0,
                                          float re_a, float im_a, float re_b, float im_b) {
    float pr  = (re_a + re_b) * SC;
    float pi  = (im_a + im_b) * SC;
    float qi  = (im_a - im_b) * SC;
    float nqr = (re_b - re_a) * SC;
    float* p = plane + r0 * W + c0;
    *reinterpret_cast<float2*>(p)     = make_float2(pr, pi);
    *reinterpret_cast<float2*>(p + W) = make_float2(qi, nqr);
}

__global__ void kE0(const float* __restrict__ high0) {
    int k2 = threadIdx.x;   // 0..255
    int i2 = blockIdx.x;    // 0..255
    int b  = blockIdx.y;
    const float4* p4 = reinterpret_cast<const float4*>(high0 + (((b * 256) + i2) * 256 + k2) * 36);
    float v[36];
#pragma unroll
    for (int t = 0; t < 9; t++) {
        float4 f = __ldg(p4 + t);
        v[4 * t] = f.x; v[4 * t + 1] = f.y; v[4 * t + 2] = f.z; v[4 * t + 3] = f.w;
    }
    int r0 = 2 * i2, c0 = 2 * k2;
#pragma unroll
    for (int c = 0; c < 3; c++) {
        c2q_store(g_LH0 + (c * 8 + b) * P512, 512, r0, c0,
                  v[c], v[18 + c], v[15 + c], v[33 + c]);
        c2q_store(g_HL0 + (c * 8 + b) * P512, 512, r0, c0,
                  v[6 + c], v[24 + c], v[9 + c], v[27 + c]);
        c2q_store(g_HH0 + (c * 8 + b) * P512, 512, r0, c0,
                  v[3 + c], v[21 + c], v[12 + c], v[30 + c]);
    }
}

__global__ void kE1(const float* __restrict__ high1) {
    int k2 = threadIdx.x;   // 0..127
    int i2 = blockIdx.x;    // 0..127
    int b  = blockIdx.y;
    const float4* p4 = reinterpret_cast<const float4*>(high1 + (((b * 128) + i2) * 128 + k2) * 36);
    float v[36];
#pragma unroll
    for (int t = 0; t < 9; t++) {
        float4 f = __ldg(p4 + t);
        v[4 * t] = f.x; v[4 * t + 1] = f.y; v[4 * t + 2] = f.z; v[4 * t + 3] = f.w;
    }
    int r0 = 2 * i2, c0 = 2 * k2;
#pragma unroll
    for (int c = 0; c < 3; c++) {
        c2q_store(g_LH1 + (c * 8 + b) * P256, 256, r0, c0,
                  v[c], v[18 + c], v[15 + c], v[33 + c]);
        c2q_store(g_HL1 + (c * 8 + b) * P256, 256, r0, c0,
                  v[6 + c], v[24 + c], v[9 + c], v[27 + c]);
        c2q_store(g_HH1 + (c * 8 + b) * P256, 256, r0, c0,
                  v[3 + c], v[21 + c], v[12 + c], v[30 + c]);
    }
}

// ---------------- colifilt cores ----------------
__device__ __forceinline__ void colifilt4(const float L[14], const float H[14], float o[4]) {
    float a0 = 0.f, a1 = 0.f, a2 = 0.f, a3 = 0.f;
#pragma unroll
    for (int j = 0; j < 7; j++) {
        float le = L[12 - 2 * j], lo = L[13 - 2 * j];
        float he = H[12 - 2 * j], ho = H[13 - 2 * j];
        a0 += cG0B_E[j] * le + cG1B_E[j] * ho;
        a1 += cG0A_E[j] * lo + cG1A_E[j] * he;
        a2 += cG0B_O[j] * le + cG1B_O[j] * ho;
        a3 += cG0A_O[j] * lo + cG1A_O[j] * he;
    }
    o[0] = a0; o[1] = a1; o[2] = a2; o[3] = a3;
}

__device__ __forceinline__ void colifilt4v(const float2 L[14], const float2 H[14], float2 o[4]) {
    float2 a0 = {0.f,0.f}, a1 = {0.f,0.f}, a2 = {0.f,0.f}, a3 = {0.f,0.f};
#pragma unroll
    for (int j = 0; j < 7; j++) {
        float2 le = L[12 - 2 * j], lo = L[13 - 2 * j];
        float2 he = H[12 - 2 * j], ho = H[13 - 2 * j];
        a0.x += cG0B_E[j] * le.x + cG1B_E[j] * ho.x;  a0.y += cG0B_E[j] * le.y + cG1B_E[j] * ho.y;
        a1.x += cG0A_E[j] * lo.x + cG1A_E[j] * he.x;  a1.y += cG0A_E[j] * lo.y + cG1A_E[j] * he.y;
        a2.x += cG0B_O[j] * le.x + cG1B_O[j] * ho.x;  a2.y += cG0B_O[j] * le.y + cG1B_O[j] * ho.y;
        a3.x += cG0A_O[j] * lo.x + cG1A_O[j] * he.x;  a3.y += cG0A_O[j] * lo.y + cG1A_O[j] * he.y;
    }
    o[0] = a0; o[1] = a1; o[2] = a2; o[3] = a3;
}

// ---------------- biort cores ----------------
__device__ __forceinline__ void biort4(const float W0[10], const float W1[8], float o[4]) {
#pragma unroll
    for (int s = 0; s < 4; s++) {
        float a = 0.f;
#pragma unroll
        for (int j = 0; j < 7; j++) a += cG0O[j] * W0[s + 6 - j];
#pragma unroll
        for (int j = 0; j < 5; j++) a += cG1O[j] * W1[s + 4 - j];
        o[s] = a;
    }
}

__device__ __forceinline__ void biort4v(const float4 W0[10], const float4 W1[8], float4 o[4]) {
#pragma unroll
    for (int s = 0; s < 4; s++) {
        float4 a = {0.f,0.f,0.f,0.f};
#pragma unroll
        for (int j = 0; j < 7; j++) {
            float g = cG0O[j]; float4 v = W0[s + 6 - j];
            a.x += g * v.x; a.y += g * v.y; a.z += g * v.z; a.w += g * v.w;
        }
#pragma unroll
        for (int j = 0; j < 5; j++) {
            float g = cG1O[j]; float4 v = W1[s + 4 - j];
            a.x += g * v.x; a.y += g * v.y; a.z += g * v.z; a.w += g * v.w;
        }
        o[s] = a;
    }
}

// ---------------- kF1: fused level-1 (rows then cols) ----------------
// Block: 128 threads, (q, cb). Phase 1: row colifilt (float2, 2 cols/thread)
// -> smem y strip (4 rows x 256). Phase 2: column colifilt from smem -> Z.
__global__ void kF1() {
    __shared__ float sy1[4][256];
    __shared__ float sy2[4][256];
    int tid = threadIdx.x;   // 0..127
    int w2 = 2 * tid;
    int q  = blockIdx.x;     // 0..127
    int cb = blockIdx.y;     // 0..23
    int r0 = 2 * q - 6;

    int rows[14];
#pragma unroll
    for (int t = 0; t < 14; t++) rows[t] = refl(r0 + t, 256) * 256;

    float2 L[14], H[14], o2[4];
    // ---- y1 = colifilt(lowp, G0) + colifilt(LH1, G1) ----
    {
        const float* pl = g_lowp + cb * P256 + w2;
        const float* ph = g_LH1  + cb * P256 + w2;
#pragma unroll
        for (int t = 0; t < 14; t++) {
            L[t] = *reinterpret_cast<const float2*>(pl + rows[t]);
            H[t] = *reinterpret_cast<const float2*>(ph + rows[t]);
        }
        colifilt4v(L, H, o2);
#pragma unroll
        for (int s = 0; s < 4; s++) *reinterpret_cast<float2*>(&sy1[s][w2]) = o2[s];
    }
    // ---- y2 = colifilt(HL1, G0) + colifilt(HH1, G1) ----
    {
        const float* pl = g_HL1 + cb * P256 + w2;
        const float* ph = g_HH1 + cb * P256 + w2;
#pragma unroll
        for (int t = 0; t < 14; t++) {
            L[t] = *reinterpret_cast<const float2*>(pl + rows[t]);
            H[t] = *reinterpret_cast<const float2*>(ph + rows[t]);
        }
        colifilt4v(L, H, o2);
#pragma unroll
        for (int s = 0; s < 4; s++) *reinterpret_cast<float2*>(&sy2[s][w2]) = o2[s];
    }
    __syncthreads();
    // ---- phase 2: column colifilt; s = rep, qc = tid ----
    float* zb = g_Z + cb * P512 + (4 * q) * 512;
    int qc = tid;
    int c0 = 2 * qc - 6;
    bool interior = (qc >= 3 && qc <= 124);
#pragma unroll
    for (int s = 0; s < 4; s++) {
        float W1[14], W2[14], o[4];
        if (interior) {
#pragma unroll
            for (int t = 0; t < 7; t++) {
                float2 u = *reinterpret_cast<const float2*>(&sy1[s][c0 + 2 * t]);
                W1[2 * t] = u.x; W1[2 * t + 1] = u.y;
                float2 v = *reinterpret_cast<const float2*>(&sy2[s][c0 + 2 * t]);
                W2[2 * t] = v.x; W2[2 * t + 1] = v.y;
            }
        } else {
#pragma unroll
            for (int t = 0; t < 14; t++) {
                int cc = refl(c0 + t, 256);
                W1[t] = sy1[s][cc]; W2[t] = sy2[s][cc];
            }
        }
        colifilt4(W1, W2, o);
        *reinterpret_cast<float4*>(zb + s * 512 + 4 * qc) = make_float4(o[0], o[1], o[2], o[3]);
    }
}

// ---------------- kF2: fused level-0 (rows then cols) -> output ----------------
// Block: 128 threads, (it, b). Phase 1: row biort (float4, 4 cols/thread)
// -> smem t strips (3ch x 4 rows x 512). Phase 2: column biort -> out.
__global__ void kF2(float* __restrict__ out) {
    __shared__ float st1[3][4][512];
    __shared__ float st2[3][4][512];
    int tid = threadIdx.x;   // 0..127
    int it = blockIdx.x;     // 0..127
    int b  = blockIdx.y;     // 0..7
    int i0 = 4 * it;
    int w4 = 4 * tid;

    int r0t[10], r1t[8];
#pragma unroll
    for (int t = 0; t < 10; t++) r0t[t] = refl(i0 - 3 + t, 512) * 512;
#pragma unroll
    for (int t = 0; t < 8; t++)  r1t[t] = refl(i0 - 2 + t, 512) * 512;

#pragma unroll
    for (int c = 0; c < 3; c++) {
        int pb = c * 8 + b;
        float4 W0[10], W1[8], o[4];
        // t1 = colfilter(Z,g0) + colfilter(LH0,g1)
        {
            const float* pZ = g_Z   + pb * P512 + w4;
            const float* pL = g_LH0 + pb * P512 + w4;
#pragma unroll
            for (int t = 0; t < 10; t++) W0[t] = *reinterpret_cast<const float4*>(pZ + r0t[t]);
#pragma unroll
            for (int t = 0; t < 8; t++)  W1[t] = *reinterpret_cast<const float4*>(pL + r1t[t]);
            biort4v(W0, W1, o);
#pragma unroll
            for (int s = 0; s < 4; s++) *reinterpret_cast<float4*>(&st1[c][s][w4]) = o[s];
        }
        // t2 = colfilter(HL0,g0) + colfilter(HH0,g1)
        {
            const float* pZ = g_HL0 + pb * P512 + w4;
            const float* pL = g_HH0 + pb * P512 + w4;
#pragma unroll
            for (int t = 0; t < 10; t++) W0[t] = *reinterpret_cast<const float4*>(pZ + r0t[t]);
#pragma unroll
            for (int t = 0; t < 8; t++)  W1[t] = *reinterpret_cast<const float4*>(pL + r1t[t]);
            biort4v(W0, W1, o);
#pragma unroll
            for (int s = 0; s < 4; s++) *reinterpret_cast<float4*>(&st2[c][s][w4]) = o[s];
        }
    }
    __syncthreads();
    // ---- phase 2: column biort; s = rep, kg = tid ----
    int kg = tid;
    int k0 = 4 * kg;
    bool interior = (kg >= 1 && kg <= 126);
#pragma unroll
    for (int s = 0; s < 4; s++) {
        float res[12];
        float W0[10], W1[8], o[4];
        if (interior) {
#pragma unroll
            for (int c = 0; c < 3; c++) {
                const float4* p1 = reinterpret_cast<const float4*>(&st1[c][s][k0 - 4]);
                const float4* p2 = reinterpret_cast<const float4*>(&st2[c][s][k0 - 4]);
                float4 a0 = p1[0], a1 = p1[1], a2 = p1[2];
                float4 b0 = p2[0], b1 = p2[1], b2 = p2[2];
                float V0[12] = {a0.x,a0.y,a0.z,a0.w, a1.x,a1.y,a1.z,a1.w, a2.x,a2.y,a2.z,a2.w};
                float V1[12] = {b0.x,b0.y,b0.z,b0.w, b1.x,b1.y,b1.z,b1.w, b2.x,b2.y,b2.z,b2.w};
                biort4(&V0[1], &V1[2], o);
                res[c] = o[0]; res[3 + c] = o[1]; res[6 + c] = o[2]; res[9 + c] = o[3];
            }
        } else {
#pragma unroll
            for (int c = 0; c < 3; c++) {
                const float* p1 = st1[c][s];
                const float* p2 = st2[c][s];
#pragma unroll
                for (int t = 0; t < 10; t++) W0[t] = p1[refl(k0 - 3 + t, 512)];
#pragma unroll
                for (int t = 0; t < 8; t++)  W1[t] = p2[refl(k0 - 2 + t, 512)];
                biort4(W0, W1, o);
                res[c] = o[0]; res[3 + c] = o[1]; res[6 + c] = o[2]; res[9 + c] = o[3];
            }
        }
        float4* po = reinterpret_cast<float4*>(out + (((b * 512) + (i0 + s)) * 512 + k0) * 3);
        po[0] = make_float4(res[0], res[1], res[2],  res[3]);
        po[1] = make_float4(res[4], res[5], res[6],  res[7]);
        po[2] = make_float4(res[8], res[9], res[10], res[11]);
    }
}

// ---------------- launch ----------------
extern "C" void kernel_launch(void* const* d_in, const int* in_sizes, int n_in,
                              void* d_out, int out_size) {
    const float* low   = (const float*)d_in[0];
    const float* high0 = (const float*)d_in[1];
    const float* high1 = (const float*)d_in[2];
    float* out = (float*)d_out;

    kP <<<dim3(256, 8), 64>>>(low);
    kE1<<<dim3(128, 8), 128>>>(high1);
    kE0<<<dim3(256, 8), 256>>>(high0);
    kF1<<<dim3(128, 24), 128>>>();
    kF2<<<dim3(128, 8), 128>>>(out);
}

// round 14
// speedup vs baseline: 1.0596x; 1.0596x over previous
#include <cuda_runtime.h>

#define SC 0.70710678118654752f

// ---------------- filter constants ----------------
__constant__ float cG0B_E[7] = { 0.00325314f,  0.03466035f, -0.11720389f,  0.75614564f,  0.01186609f,  0.02382538f, -0.00543948f};
__constant__ float cG0B_O[7] = {-0.00388321f, -0.03887280f,  0.27529538f,  0.56881042f, -0.10671180f,  0.01702522f, -0.00455690f};
__constant__ float cG0A_E[7] = {-0.00455690f,  0.01702522f, -0.10671180f,  0.56881042f,  0.27529538f, -0.03887280f, -0.00388321f};
__constant__ float cG0A_O[7] = {-0.00543948f,  0.02382538f,  0.01186609f,  0.75614564f, -0.11720389f,  0.03466035f,  0.00325314f};
__constant__ float cG1B_E[7] = {-0.00455690f,  0.01702522f, -0.10671180f,  0.56881042f,  0.27529538f, -0.03887280f, -0.00388321f};
__constant__ float cG1B_O[7] = { 0.00543948f, -0.02382538f, -0.01186609f, -0.75614564f,  0.11720389f, -0.03466035f, -0.00325314f};
__constant__ float cG1A_E[7] = {-0.00325314f, -0.03466035f,  0.11720389f, -0.75614564f, -0.01186609f, -0.02382538f,  0.00543948f};
__constant__ float cG1A_O[7] = {-0.00388321f, -0.03887280f,  0.27529538f,  0.56881042f, -0.10671180f,  0.01702522f, -0.00455690f};

__constant__ float cG0O[7] = {-0.0107142857142857f, -0.0535714285714286f, 0.2607142857142857f,
                               0.6071428571428571f,  0.2607142857142857f, -0.0535714285714286f,
                              -0.0107142857142857f};
__constant__ float cG1O[5] = {-0.05f, -0.25f, 0.6f, -0.25f, -0.05f};

// ---------------- planar scratch [c][b][H][W] ----------------
#define P256 (256*256)
#define P512 (512*512)
__device__ float g_lowp[3*8*P256];
__device__ float g_LH1[3*8*P256];
__device__ float g_HL1[3*8*P256];
__device__ float g_HH1[3*8*P256];
__device__ float g_Z [3*8*P512];
__device__ float g_LH0[3*8*P512];
__device__ float g_HL0[3*8*P512];
__device__ float g_HH0[3*8*P512];

__device__ __forceinline__ int refl(int x, int L) {
    x = (x < 0) ? (-1 - x) : x;
    return (x >= L) ? (2 * L - 1 - x) : x;
}

// ---------------- kP: planarize low ----------------
__global__ void kP(const float* __restrict__ low) {
    int wt = threadIdx.x;         // 0..63
    int i  = blockIdx.x;          // 0..255
    int b  = blockIdx.y;          // 0..7
    const float4* p = reinterpret_cast<const float4*>(low + (((b * 256) + i) * 256 + 4 * wt) * 3);
    float4 v0 = __ldg(p), v1 = __ldg(p + 1), v2 = __ldg(p + 2);
    int o = i * 256 + 4 * wt;
    *reinterpret_cast<float4*>(g_lowp + (0 * 8 + b) * P256 + o) = make_float4(v0.x, v0.w, v1.z, v2.y);
    *reinterpret_cast<float4*>(g_lowp + (1 * 8 + b) * P256 + o) = make_float4(v0.y, v1.x, v1.w, v2.z);
    *reinterpret_cast<float4*>(g_lowp + (2 * 8 + b) * P256 + o) = make_float4(v0.z, v1.y, v2.x, v2.w);
}

// ---------------- c2q expansion (smem-staged, coalesced reads) ----------------
__device__ __forceinline__ void c2q_store(float* plane, int W, int r0, int c0,
                                          float re_a, float im_a, float re_b, float im_b) {
    float pr  = (re_a + re_b) * SC;
    float pi  = (im_a + im_b) * SC;
    float qi  = (im_a - im_b) * SC;
    float nqr = (re_b - re_a) * SC;
    float* p = plane + r0 * W + c0;
    *reinterpret_cast<float2*>(p)     = make_float2(pr, pi);
    *reinterpret_cast<float2*>(p + W) = make_float2(qi, nqr);
}

// Block: 256 threads, one 64-pixel tile of one input row.
// Phase 1: coalesced bulk-load 64*36 floats into padded smem.
// Phase 2: 192 threads (64 pixels x 3 channels) do c2q stores.
template<int HW>   // HW = input spatial size (256 for high0, 128 for high1)
__device__ __forceinline__ void expand_tile(const float* __restrict__ hi,
                                            float* pLH, float* pHL, float* pHH) {
    __shared__ float s[64][37];
    int tid = threadIdx.x;
    int k2t = blockIdx.x;   // tile index
    int i2  = blockIdx.y;   // input row
    int b   = blockIdx.z;
    const int W2 = 2 * HW;
    const float4* src = reinterpret_cast<const float4*>(hi + (((b * HW) + i2) * HW + k2t * 64) * 36);
#pragma unroll
    for (int l = tid; l < 576; l += 256) {
        float4 f = __ldg(src + l);
        int base = 4 * l;
        float vv[4] = {f.x, f.y, f.z, f.w};
#pragma unroll
        for (int j = 0; j < 4; j++) {
            int idx = base + j;
            int pp = idx / 36;
            s[pp][idx - pp * 36] = vv[j];
        }
    }
    __syncthreads();
    if (tid < 192) {
        int pix = tid & 63;
        int c   = tid >> 6;
        const float* v = s[pix];
        int r0 = 2 * i2;
        int c0 = 2 * (k2t * 64 + pix);
        int pb = (c * 8 + b) * (W2 * W2);
        // LH: pair(0,5); HL: pair(2,3); HH: pair(1,4)
        c2q_store(pLH + pb, W2, r0, c0, v[c],     v[18 + c], v[15 + c], v[33 + c]);
        c2q_store(pHL + pb, W2, r0, c0, v[6 + c], v[24 + c], v[9 + c],  v[27 + c]);
        c2q_store(pHH + pb, W2, r0, c0, v[3 + c], v[21 + c], v[12 + c], v[30 + c]);
    }
}

__global__ void kE0(const float* __restrict__ high0) {
    expand_tile<256>(high0, g_LH0, g_HL0, g_HH0);
}
__global__ void kE1(const float* __restrict__ high1) {
    expand_tile<128>(high1, g_LH1, g_HL1, g_HH1);
}

// ---------------- colifilt cores ----------------
__device__ __forceinline__ void colifilt4(const float L[14], const float H[14], float o[4]) {
    float a0 = 0.f, a1 = 0.f, a2 = 0.f, a3 = 0.f;
#pragma unroll
    for (int j = 0; j < 7; j++) {
        float le = L[12 - 2 * j], lo = L[13 - 2 * j];
        float he = H[12 - 2 * j], ho = H[13 - 2 * j];
        a0 += cG0B_E[j] * le + cG1B_E[j] * ho;
        a1 += cG0A_E[j] * lo + cG1A_E[j] * he;
        a2 += cG0B_O[j] * le + cG1B_O[j] * ho;
        a3 += cG0A_O[j] * lo + cG1A_O[j] * he;
    }
    o[0] = a0; o[1] = a1; o[2] = a2; o[3] = a3;
}

__device__ __forceinline__ void colifilt4v(const float2 L[14], const float2 H[14], float2 o[4]) {
    float2 a0 = {0.f,0.f}, a1 = {0.f,0.f}, a2 = {0.f,0.f}, a3 = {0.f,0.f};
#pragma unroll
    for (int j = 0; j < 7; j++) {
        float2 le = L[12 - 2 * j], lo = L[13 - 2 * j];
        float2 he = H[12 - 2 * j], ho = H[13 - 2 * j];
        a0.x += cG0B_E[j] * le.x + cG1B_E[j] * ho.x;  a0.y += cG0B_E[j] * le.y + cG1B_E[j] * ho.y;
        a1.x += cG0A_E[j] * lo.x + cG1A_E[j] * he.x;  a1.y += cG0A_E[j] * lo.y + cG1A_E[j] * he.y;
        a2.x += cG0B_O[j] * le.x + cG1B_O[j] * ho.x;  a2.y += cG0B_O[j] * le.y + cG1B_O[j] * ho.y;
        a3.x += cG0A_O[j] * lo.x + cG1A_O[j] * he.x;  a3.y += cG0A_O[j] * lo.y + cG1A_O[j] * he.y;
    }
    o[0] = a0; o[1] = a1; o[2] = a2; o[3] = a3;
}

// ---------------- biort cores ----------------
__device__ __forceinline__ void biort4(const float W0[10], const float W1[8], float o[4]) {
#pragma unroll
    for (int s = 0; s < 4; s++) {
        float a = 0.f;
#pragma unroll
        for (int j = 0; j < 7; j++) a += cG0O[j] * W0[s + 6 - j];
#pragma unroll
        for (int j = 0; j < 5; j++) a += cG1O[j] * W1[s + 4 - j];
        o[s] = a;
    }
}

__device__ __forceinline__ void biort4v2(const float2 W0[10], const float2 W1[8], float2 o[4]) {
#pragma unroll
    for (int s = 0; s < 4; s++) {
        float2 a = {0.f, 0.f};
#pragma unroll
        for (int j = 0; j < 7; j++) {
            float g = cG0O[j]; float2 v = W0[s + 6 - j];
            a.x += g * v.x; a.y += g * v.y;
        }
#pragma unroll
        for (int j = 0; j < 5; j++) {
            float g = cG1O[j]; float2 v = W1[s + 4 - j];
            a.x += g * v.x; a.y += g * v.y;
        }
        o[s] = a;
    }
}

// ---------------- kF1: fused level-1, split-half ----------------
// 256 threads: tid<128 computes y1 (lowp+LH1), tid>=128 computes y2 (HL1+HH1).
__global__ void kF1() {
    __shared__ float sy[2][4][256];
    int tid = threadIdx.x;
    int half = tid >> 7;       // 0 -> y1, 1 -> y2
    int t = tid & 127;
    int w2 = 2 * t;
    int q  = blockIdx.x;       // 0..127
    int cb = blockIdx.y;       // 0..23
    int r0 = 2 * q - 6;

    const float* pl = (half ? g_HL1 : g_lowp) + cb * P256 + w2;
    const float* ph = (half ? g_HH1 : g_LH1)  + cb * P256 + w2;

    float2 L[14], H[14], o2[4];
    if (q >= 3 && q <= 124) {
#pragma unroll
        for (int u = 0; u < 14; u++) {
            L[u] = *reinterpret_cast<const float2*>(pl + (r0 + u) * 256);
            H[u] = *reinterpret_cast<const float2*>(ph + (r0 + u) * 256);
        }
    } else {
#pragma unroll
        for (int u = 0; u < 14; u++) {
            int rr = refl(r0 + u, 256) * 256;
            L[u] = *reinterpret_cast<const float2*>(pl + rr);
            H[u] = *reinterpret_cast<const float2*>(ph + rr);
        }
    }
    colifilt4v(L, H, o2);
#pragma unroll
    for (int s = 0; s < 4; s++) *reinterpret_cast<float2*>(&sy[half][s][w2]) = o2[s];
    __syncthreads();

    // phase 2: 512 tasks (4 s x 128 qc) over 256 threads
    float* zb = g_Z + cb * P512 + (4 * q) * 512;
#pragma unroll
    for (int rep = 0; rep < 2; rep++) {
        int task = tid + 256 * rep;
        int s = task >> 7, qc = task & 127;
        int c0 = 2 * qc - 6;
        float W1[14], W2[14], o[4];
        if (qc >= 3 && qc <= 124) {
#pragma unroll
            for (int u = 0; u < 7; u++) {
                float2 a = *reinterpret_cast<const float2*>(&sy[0][s][c0 + 2 * u]);
                W1[2 * u] = a.x; W1[2 * u + 1] = a.y;
                float2 bvl = *reinterpret_cast<const float2*>(&sy[1][s][c0 + 2 * u]);
                W2[2 * u] = bvl.x; W2[2 * u + 1] = bvl.y;
            }
        } else {
#pragma unroll
            for (int u = 0; u < 14; u++) {
                int cc = refl(c0 + u, 256);
                W1[u] = sy[0][s][cc]; W2[u] = sy[1][s][cc];
            }
        }
        colifilt4(W1, W2, o);
        *reinterpret_cast<float4*>(zb + s * 512 + 4 * qc) = make_float4(o[0], o[1], o[2], o[3]);
    }
}

// ---------------- kF2: fused level-0, split-half -> output ----------------
// 512 threads: tid<256 computes t1 (Z+LH0), tid>=256 computes t2 (HL0+HH0),
// float2 (2 cols/thread), looping 3 channels.
__global__ void kF2(float* __restrict__ out) {
    __shared__ float st[2][3][4][512];
    int tid = threadIdx.x;
    int it = blockIdx.x;     // 0..127
    int b  = blockIdx.y;     // 0..7
    int i0 = 4 * it;
    int half = tid >> 8;     // 0 -> t1, 1 -> t2
    int cp = tid & 255;
    int w2 = 2 * cp;
    bool interiorR = (it >= 1 && it <= 126);

#pragma unroll
    for (int c = 0; c < 3; c++) {
        int pb = c * 8 + b;
        const float* p0 = (half ? g_HL0 : g_Z)   + pb * P512 + w2;
        const float* p1 = (half ? g_HH0 : g_LH0) + pb * P512 + w2;
        float2 W0[10], W1[8], o2[4];
        if (interiorR) {
#pragma unroll
            for (int u = 0; u < 10; u++) W0[u] = *reinterpret_cast<const float2*>(p0 + (i0 - 3 + u) * 512);
#pragma unroll
            for (int u = 0; u < 8; u++)  W1[u] = *reinterpret_cast<const float2*>(p1 + (i0 - 2 + u) * 512);
        } else {
#pragma unroll
            for (int u = 0; u < 10; u++) W0[u] = *reinterpret_cast<const float2*>(p0 + refl(i0 - 3 + u, 512) * 512);
#pragma unroll
            for (int u = 0; u < 8; u++)  W1[u] = *reinterpret_cast<const float2*>(p1 + refl(i0 - 2 + u, 512) * 512);
        }
        biort4v2(W0, W1, o2);
#pragma unroll
        for (int s = 0; s < 4; s++) *reinterpret_cast<float2*>(&st[half][c][s][w2]) = o2[s];
    }
    __syncthreads();

    // phase 2: 512 tasks (4 s x 128 kg), one per thread
    int s = tid >> 7, kg = tid & 127;
    int k0 = 4 * kg;
    float res[12];
    float W0[10], W1[8], o[4];
    if (kg >= 1 && kg <= 126) {
#pragma unroll
        for (int c = 0; c < 3; c++) {
            const float4* p1 = reinterpret_cast<const float4*>(&st[0][c][s][k0 - 4]);
            const float4* p2 = reinterpret_cast<const float4*>(&st[1][c][s][k0 - 4]);
            float4 a0 = p1[0], a1 = p1[1], a2 = p1[2];
            float4 b0 = p2[0], b1 = p2[1], b2 = p2[2];
            float V0[12] = {a0.x,a0.y,a0.z,a0.w, a1.x,a1.y,a1.z,a1.w, a2.x,a2.y,a2.z,a2.w};
            float V1[12] = {b0.x,b0.y,b0.z,b0.w, b1.x,b1.y,b1.z,b1.w, b2.x,b2.y,b2.z,b2.w};
            biort4(&V0[1], &V1[2], o);
            res[c] = o[0]; res[3 + c] = o[1]; res[6 + c] = o[2]; res[9 + c] = o[3];
        }
    } else {
#pragma unroll
        for (int c = 0; c < 3; c++) {
            const float* p1 = st[0][c][s];
            const float* p2 = st[1][c][s];
#pragma unroll
            for (int u = 0; u < 10; u++) W0[u] = p1[refl(k0 - 3 + u, 512)];
#pragma unroll
            for (int u = 0; u < 8; u++)  W1[u] = p2[refl(k0 - 2 + u, 512)];
            biort4(W0, W1, o);
            res[c] = o[0]; res[3 + c] = o[1]; res[6 + c] = o[2]; res[9 + c] = o[3];
        }
    }
    float4* po = reinterpret_cast<float4*>(out + (((b * 512) + (i0 + s)) * 512 + k0) * 3);
    po[0] = make_float4(res[0], res[1], res[2],  res[3]);
    po[1] = make_float4(res[4], res[5], res[6],  res[7]);
    po[2] = make_float4(res[8], res[9], res[10], res[11]);
}

// ---------------- launch ----------------
extern "C" void kernel_launch(void* const* d_in, const int* in_sizes, int n_in,
                              void* d_out, int out_size) {
    const float* low   = (const float*)d_in[0];
    const float* high0 = (const float*)d_in[1];
    const float* high1 = (const float*)d_in[2];
    float* out = (float*)d_out;

    kP <<<dim3(256, 8), 64>>>(low);
    kE1<<<dim3(2, 128, 8), 256>>>(high1);
    kE0<<<dim3(4, 256, 8), 256>>>(high0);
    kF1<<<dim3(128, 24), 256>>>();
    kF2<<<dim3(128, 8), 512>>>(out);
}